// round 13
// baseline (speedup 1.0000x reference)
#include <cuda_runtime.h>
#include <math.h>

#define DIM 1024
#define NH 16
#define HD 64
#define BATCH 2
#define SEQ 2048
#define MTOT (BATCH * SEQ)   // 4096

// Scratch (device globals: allowed; no runtime allocation)
__device__ float g_xq[MTOT * DIM];
__device__ float g_xk[MTOT * DIM];
__device__ float g_xv[MTOT * DIM];
__device__ float g_xo[MTOT * DIM];
__device__ float g_wr[4 * DIM * DIM];   // tf32-rounded weights (wq,wk,wv,wo)

__device__ __forceinline__ unsigned f2tf(float x) {
    unsigned r;
    asm("cvt.rna.tf32.f32 %0, %1;" : "=r"(r) : "f"(x));
    return r;
}

__device__ __forceinline__ void mma_tf32(float* c, const unsigned* a, const unsigned* b) {
    asm volatile(
        "mma.sync.aligned.m16n8k8.row.col.f32.tf32.tf32.f32 "
        "{%0,%1,%2,%3}, {%4,%5,%6,%7}, {%8,%9}, {%0,%1,%2,%3};\n"
        : "+f"(c[0]), "+f"(c[1]), "+f"(c[2]), "+f"(c[3])
        : "r"(a[0]), "r"(a[1]), "r"(a[2]), "r"(a[3]), "r"(b[0]), "r"(b[1]));
}

__device__ __forceinline__ void ldsm_x4(unsigned& r0, unsigned& r1,
                                        unsigned& r2, unsigned& r3, unsigned addr) {
    asm volatile("ldmatrix.sync.aligned.m8n8.x4.shared.b16 {%0,%1,%2,%3}, [%4];"
                 : "=r"(r0), "=r"(r1), "=r"(r2), "=r"(r3) : "r"(addr));
}

__device__ __forceinline__ void cp_async16(void* smem_dst, const void* gptr) {
    unsigned s = (unsigned)__cvta_generic_to_shared(smem_dst);
    asm volatile("cp.async.cg.shared.global [%0], [%1], 16;\n" :: "r"(s), "l"(gptr));
}
__device__ __forceinline__ void cp_commit() {
    asm volatile("cp.async.commit_group;\n");
}
__device__ __forceinline__ void cp_wait0() { asm volatile("cp.async.wait_group 0;\n"); }
__device__ __forceinline__ void cp_wait1() { asm volatile("cp.async.wait_group 1;\n"); }
__device__ __forceinline__ void cp_wait2() { asm volatile("cp.async.wait_group 2;\n"); }

// ---------------------------------------------------------------------------
// Pre-round weights to tf32.
// ---------------------------------------------------------------------------
__global__ void __launch_bounds__(256) round_w(
    const float4* __restrict__ w0, const float4* __restrict__ w1,
    const float4* __restrict__ w2, const float4* __restrict__ w3,
    float4* __restrict__ dst)
{
    const int y = blockIdx.y;
    const float4* src = (y == 0) ? w0 : (y == 1) ? w1 : (y == 2) ? w2 : w3;
    const int i = blockIdx.x * 256 + threadIdx.x;
    float4 v = src[i];
    float4 r;
    r.x = __uint_as_float(f2tf(v.x));
    r.y = __uint_as_float(f2tf(v.y));
    r.z = __uint_as_float(f2tf(v.z));
    r.w = __uint_as_float(f2tf(v.w));
    dst[(size_t)y * (DIM * DIM / 4) + i] = r;
}

// ---------------------------------------------------------------------------
// TF32 NT GEMM (unchanged from R9): CTA 128x128, 128 threads, 3-stage
// cp.async, register fragment double-buffering, 2 CTAs/SM.
// ---------------------------------------------------------------------------
#define GLD 36
#define STG ((128 + 128) * GLD)
#define GEMM_SMEM (3 * STG * 4)   // 110592 bytes

template <int CVT_A, int ROUND_OUT>
__global__ void __launch_bounds__(128, 2) gemm_tc(
    const float* __restrict__ A0, const float* __restrict__ A1, const float* __restrict__ A2,
    const float* __restrict__ W0, const float* __restrict__ W1, const float* __restrict__ W2,
    float* __restrict__ C0, float* __restrict__ C1, float* __restrict__ C2,
    int M, int N, int K)
{
    extern __shared__ float smg[];
    const int z = blockIdx.z;
    const float* A = (z == 0) ? A0 : (z == 1) ? A1 : A2;
    const float* W = (z == 0) ? W0 : (z == 1) ? W1 : W2;
    float* C = (z == 0) ? C0 : (z == 1) ? C1 : C2;

    const int tid = threadIdx.x;
    const int warp = tid >> 5, lane = tid & 31;
    const int g = lane >> 2, t = lane & 3;
    const int lm = lane >> 3, lr8 = lane & 7;
    const int wm = (warp & 1) * 64;
    const int wn = (warp >> 1) * 64;
    const int bm = blockIdx.y * 128, bn = blockIdx.x * 128;

    const unsigned smem_u = (unsigned)__cvta_generic_to_shared(smg);
    const unsigned aoff = ((wm + (lm & 1) * 8 + lr8) * GLD + (lm >> 1) * 4) * 4;
    const unsigned boff = ((wn + (lm >> 1) * 8 + lr8) * GLD + (lm & 1) * 4) * 4;

    float acc[4][8][4] = {};

    auto load_stage = [&](int s) {
        float* As = smg + (s % 3) * STG;
        float* Bs = As + 128 * GLD;
        const int k0 = s * 32;
#pragma unroll
        for (int j = 0; j < 8; j++) {
            const int cid = tid + j * 128;
            const int row = cid >> 3, c4 = (cid & 7) * 4;
            cp_async16(As + row * GLD + c4, A + (size_t)(bm + row) * K + k0 + c4);
        }
#pragma unroll
        for (int j = 0; j < 8; j++) {
            const int cid = tid + j * 128;
            const int row = cid >> 3, c4 = (cid & 7) * 4;
            cp_async16(Bs + row * GLD + c4, W + (size_t)(bn + row) * K + k0 + c4);
        }
        cp_commit();
    };

    load_stage(0);
    load_stage(1);

    unsigned afr[2][4][4], bfr[2][8][2];

    const int niter = K / 32;
#pragma unroll 1
    for (int it = 0; it < niter; it++) {
        if (it + 1 < niter) cp_wait1(); else cp_wait0();
        __syncthreads();
        if (it + 2 < niter) load_stage(it + 2);

        const unsigned Ab = smem_u + (it % 3) * STG * 4 + aoff;
        const unsigned Bb = smem_u + ((it % 3) * STG + 128 * GLD) * 4 + boff;

#pragma unroll
        for (int mt = 0; mt < 4; mt++) {
            ldsm_x4(afr[0][mt][0], afr[0][mt][1], afr[0][mt][2], afr[0][mt][3],
                    Ab + (mt * 16 * GLD) * 4);
            if (CVT_A) {
#pragma unroll
                for (int r = 0; r < 4; r++)
                    afr[0][mt][r] = f2tf(__uint_as_float(afr[0][mt][r]));
            }
        }
#pragma unroll
        for (int ntp = 0; ntp < 4; ntp++)
            ldsm_x4(bfr[0][2 * ntp][0], bfr[0][2 * ntp][1],
                    bfr[0][2 * ntp + 1][0], bfr[0][2 * ntp + 1][1],
                    Bb + (ntp * 16 * GLD) * 4);

#pragma unroll
        for (int ks = 0; ks < 4; ks++) {
            const int cur = ks & 1, nxt = cur ^ 1;
            if (ks < 3) {
#pragma unroll
                for (int mt = 0; mt < 4; mt++) {
                    ldsm_x4(afr[nxt][mt][0], afr[nxt][mt][1],
                            afr[nxt][mt][2], afr[nxt][mt][3],
                            Ab + (mt * 16 * GLD + (ks + 1) * 8) * 4);
                    if (CVT_A) {
#pragma unroll
                        for (int r = 0; r < 4; r++)
                            afr[nxt][mt][r] = f2tf(__uint_as_float(afr[nxt][mt][r]));
                    }
                }
#pragma unroll
                for (int ntp = 0; ntp < 4; ntp++)
                    ldsm_x4(bfr[nxt][2 * ntp][0], bfr[nxt][2 * ntp][1],
                            bfr[nxt][2 * ntp + 1][0], bfr[nxt][2 * ntp + 1][1],
                            Bb + (ntp * 16 * GLD + (ks + 1) * 8) * 4);
            }
#pragma unroll
            for (int mt = 0; mt < 4; mt++)
#pragma unroll
                for (int nt = 0; nt < 8; nt++)
                    mma_tf32(acc[mt][nt], afr[cur][mt], bfr[cur][nt]);
        }
    }

#pragma unroll
    for (int mt = 0; mt < 4; mt++)
#pragma unroll
        for (int nt = 0; nt < 8; nt++) {
            const int row = bm + wm + mt * 16 + g;
            const int col = bn + wn + nt * 8 + 2 * t;
            float v0 = acc[mt][nt][0], v1 = acc[mt][nt][1];
            float v2 = acc[mt][nt][2], v3 = acc[mt][nt][3];
            if (ROUND_OUT) {
                v0 = __uint_as_float(f2tf(v0)); v1 = __uint_as_float(f2tf(v1));
                v2 = __uint_as_float(f2tf(v2)); v3 = __uint_as_float(f2tf(v3));
            }
            *(float2*)&C[(size_t)row * N + col] = make_float2(v0, v1);
            *(float2*)&C[(size_t)(row + 8) * N + col] = make_float2(v2, v3);
        }
}

// ---------------------------------------------------------------------------
// TF32 flash attention, SOFTWARE-PIPELINED: S(kt+1) MMAs are issued inside
// iteration kt, between the softmax max/alpha chain and the exp/PV section,
// filling the softmax latency shadow with tensor work.
// FQ=128 (8 warps x 16 rows), KV tiles 64, 4-stage cp.async K/V ring.
// ---------------------------------------------------------------------------
#define FQ 128
#define FK 64
#define LDK 68
#define LDV 72
#define LDP 68
#define KBUF (FK * LDK)
#define VBUF (FK * LDV)
#define FLASH_SMEM ((4 * KBUF + 4 * VBUF + FQ * LDP) * 4)   // 178176 bytes

__global__ void __launch_bounds__(256, 1) flash_tc(
    const float* __restrict__ xq, const float* __restrict__ xk,
    const float* __restrict__ xv, float* __restrict__ xo)
{
    extern __shared__ float smf[];
    float* Kst = smf;                    // 4 * KBUF
    float* Vst = Kst + 4 * KBUF;         // 4 * VBUF
    unsigned* Ps = (unsigned*)(Vst + 4 * VBUF);   // FQ * LDP

    const int tid = threadIdx.x;
    const int warp = tid >> 5, lane = tid & 31;
    const int g = lane >> 2, t = lane & 3;
    const int lm = lane >> 3, lr8 = lane & 7;
    const int qt = gridDim.x - 1 - blockIdx.x;   // big tiles first
    const int bh = blockIdx.y;
    const int b = bh >> 4, h = bh & 15;
    const size_t base = (size_t)b * SEQ * DIM + (size_t)h * HD;
    const int qrow0 = qt * FQ + warp * 16;

    const unsigned smem_u = (unsigned)__cvta_generic_to_shared(smf);
    const unsigned koff = (((lm >> 1) * 8 + lr8) * LDK + (lm & 1) * 4) * 4;
    const unsigned poff = (unsigned)((4 * KBUF + 4 * VBUF) * 4) +
        (((warp * 16 + (lm & 1) * 8 + lr8) * LDP + (lm >> 1) * 4) * 4);

    // K/V loads: 256 threads cover 64 rows x 64 cols
    const int lr = tid >> 2;             // kv row 0..63
    const int lc = (tid & 3) * 16;       // col base
    const float* kbase = xk + base + (size_t)lr * DIM + lc;
    const float* vbase = xv + base + (size_t)lr * DIM + lc;

    const int nkt = 2 * (qt + 1);

    auto load_kv = [&](int s) {
        float* kd = Kst + (s & 3) * KBUF + lr * LDK + lc;
        float* vd = Vst + (s & 3) * VBUF + lr * LDV + lc;
        const size_t off = (size_t)s * FK * DIM;
#pragma unroll
        for (int f = 0; f < 4; f++) {
            cp_async16(kd + f * 4, kbase + off + f * 4);
            cp_async16(vd + f * 4, vbase + off + f * 4);
        }
        cp_commit();
    };

    // Prologue: stages 0..min(2, nkt-1)
    load_kv(0);
    if (nkt > 1) load_kv(1);
    if (nkt > 2) load_kv(2);

    // Q fragments (pre-rounded tf32; *0.125 exact)
    unsigned qf[8][4];
    {
        const float* q0 = xq + base + (size_t)(qrow0 + g) * DIM;
        const float* q1 = xq + base + (size_t)(qrow0 + g + 8) * DIM;
#pragma unroll
        for (int c = 0; c < 8; c++) {
            qf[c][0] = __float_as_uint(q0[8 * c + t] * 0.125f);
            qf[c][1] = __float_as_uint(q1[8 * c + t] * 0.125f);
            qf[c][2] = __float_as_uint(q0[8 * c + t + 4] * 0.125f);
            qf[c][3] = __float_as_uint(q1[8 * c + t + 4] * 0.125f);
        }
    }

    // S-tile compute: sv must be zero-initialized by caller
    auto compute_S = [&](int kt, float (*sv)[4]) {
        const unsigned Kb = smem_u + (kt & 3) * KBUF * 4 + koff;
        unsigned bfr[2][8][2];
#pragma unroll
        for (int ntp = 0; ntp < 4; ntp++)
            ldsm_x4(bfr[0][2 * ntp][0], bfr[0][2 * ntp][1],
                    bfr[0][2 * ntp + 1][0], bfr[0][2 * ntp + 1][1],
                    Kb + (ntp * 16 * LDK) * 4);
#pragma unroll
        for (int c = 0; c < 8; c++) {
            const int cur = c & 1, nxt = cur ^ 1;
            if (c < 7) {
#pragma unroll
                for (int ntp = 0; ntp < 4; ntp++)
                    ldsm_x4(bfr[nxt][2 * ntp][0], bfr[nxt][2 * ntp][1],
                            bfr[nxt][2 * ntp + 1][0], bfr[nxt][2 * ntp + 1][1],
                            Kb + (ntp * 16 * LDK + (c + 1) * 8) * 4);
            }
#pragma unroll
            for (int nt = 0; nt < 8; nt++)
                mma_tf32(sv[nt], qf[c], bfr[cur][nt]);
        }
    };

    if (nkt > 2) cp_wait2(); else cp_wait1();
    __syncthreads();

    float s_cur[8][4] = {};
    compute_S(0, s_cur);

    float o[8][4] = {};
    float m0 = -1e30f, m1 = -1e30f, l0 = 0.f, l1 = 0.f;
    unsigned* Pw = Ps + (warp * 16) * LDP;

#pragma unroll 1
    for (int kt = 0; kt < nkt; kt++) {
        // Stage management: ensure stage kt+1 arrived; recycle buffer (kt+3)&3
        if (kt + 1 < nkt) {
            if (kt + 2 < nkt) cp_wait1(); else cp_wait0();
            __syncthreads();   // all warps done reading stages kt-1 (PV) / kt (S frags)
            if (kt + 3 < nkt) load_kv(kt + 3);
        }

        const bool act  = (kt * FK <= qrow0 + 15);
        const bool actn = (kt + 1 < nkt) && ((kt + 1) * FK <= qrow0 + 15);

        // ---- softmax part A: mask, max, alpha (latency chain) ----
        float mn0 = m0, mn1 = m1, al0 = 1.f, al1 = 1.f;
        if (act) {
            if (kt * FK + FK - 1 > qrow0) {
                const int rg0 = qrow0 + g, rg1 = qrow0 + g + 8;
#pragma unroll
                for (int nt = 0; nt < 8; nt++) {
                    const int col = kt * FK + nt * 8 + 2 * t;
                    if (col > rg0)     s_cur[nt][0] = -1e30f;
                    if (col + 1 > rg0) s_cur[nt][1] = -1e30f;
                    if (col > rg1)     s_cur[nt][2] = -1e30f;
                    if (col + 1 > rg1) s_cur[nt][3] = -1e30f;
                }
            }
            float mx0 = -1e30f, mx1 = -1e30f;
#pragma unroll
            for (int nt = 0; nt < 8; nt++) {
                mx0 = fmaxf(mx0, fmaxf(s_cur[nt][0], s_cur[nt][1]));
                mx1 = fmaxf(mx1, fmaxf(s_cur[nt][2], s_cur[nt][3]));
            }
            mx0 = fmaxf(mx0, __shfl_xor_sync(0xffffffffu, mx0, 1));
            mx0 = fmaxf(mx0, __shfl_xor_sync(0xffffffffu, mx0, 2));
            mx1 = fmaxf(mx1, __shfl_xor_sync(0xffffffffu, mx1, 1));
            mx1 = fmaxf(mx1, __shfl_xor_sync(0xffffffffu, mx1, 2));
            mn0 = fmaxf(m0, mx0);
            mn1 = fmaxf(m1, mx1);
            al0 = __expf(m0 - mn0);
            al1 = __expf(m1 - mn1);
            m0 = mn0; m1 = mn1;
        }

        // ---- S(kt+1): independent tensor work in the softmax shadow ----
        float s_nxt[8][4] = {};
        if (actn) compute_S(kt + 1, s_nxt);

        if (act) {
            // ---- softmax part B: exp, P store, row sums ----
            float sum0 = 0.f, sum1 = 0.f;
#pragma unroll
            for (int nt = 0; nt < 8; nt++) {
                float p0 = __expf(s_cur[nt][0] - mn0);
                float p1 = __expf(s_cur[nt][1] - mn0);
                float p2 = __expf(s_cur[nt][2] - mn1);
                float p3 = __expf(s_cur[nt][3] - mn1);
                sum0 += p0 + p1;
                sum1 += p2 + p3;
                unsigned* pr0 = Pw + g * LDP + nt * 8 + 2 * t;
                unsigned* pr1 = Pw + (g + 8) * LDP + nt * 8 + 2 * t;
                pr0[0] = f2tf(p0); pr0[1] = f2tf(p1);
                pr1[0] = f2tf(p2); pr1[1] = f2tf(p3);
            }
            sum0 += __shfl_xor_sync(0xffffffffu, sum0, 1);
            sum0 += __shfl_xor_sync(0xffffffffu, sum0, 2);
            sum1 += __shfl_xor_sync(0xffffffffu, sum1, 1);
            sum1 += __shfl_xor_sync(0xffffffffu, sum1, 2);
            l0 = l0 * al0 + sum0;
            l1 = l1 * al1 + sum1;

#pragma unroll
            for (int nt = 0; nt < 8; nt++) {
                o[nt][0] *= al0; o[nt][1] *= al0;
                o[nt][2] *= al1; o[nt][3] *= al1;
            }
            __syncwarp();

            // ---- O += P @ V ----
            const float* Vsf = Vst + (kt & 3) * VBUF;
#pragma unroll
            for (int c = 0; c < 8; c++) {
                unsigned pafr[4];
                ldsm_x4(pafr[0], pafr[1], pafr[2], pafr[3],
                        smem_u + poff + (c * 8) * 4);
#pragma unroll
                for (int nt = 0; nt < 8; nt++) {
                    unsigned bfr2[2];
                    bfr2[0] = __float_as_uint(Vsf[(c * 8 + t) * LDV + nt * 8 + g]);
                    bfr2[1] = __float_as_uint(Vsf[(c * 8 + t + 4) * LDV + nt * 8 + g]);
                    mma_tf32(o[nt], pafr, bfr2);
                }
            }
        }

        // Rotate pipeline register state
#pragma unroll
        for (int nt = 0; nt < 8; nt++) {
            s_cur[nt][0] = s_nxt[nt][0];
            s_cur[nt][1] = s_nxt[nt][1];
            s_cur[nt][2] = s_nxt[nt][2];
            s_cur[nt][3] = s_nxt[nt][3];
        }
    }

    // Normalize and write (tf32-rounded for the O-projection GEMM)
    const float inv0 = 1.f / l0, inv1 = 1.f / l1;
#pragma unroll
    for (int nt = 0; nt < 8; nt++) {
        const int col = nt * 8 + 2 * t;
        float* d0 = xo + base + (size_t)(qrow0 + g) * DIM + col;
        float* d1 = xo + base + (size_t)(qrow0 + g + 8) * DIM + col;
        *(float2*)d0 = make_float2(__uint_as_float(f2tf(o[nt][0] * inv0)),
                                   __uint_as_float(f2tf(o[nt][1] * inv0)));
        *(float2*)d1 = make_float2(__uint_as_float(f2tf(o[nt][2] * inv1)),
                                   __uint_as_float(f2tf(o[nt][3] * inv1)));
    }
}

// ---------------------------------------------------------------------------
// Launch
// ---------------------------------------------------------------------------
extern "C" void kernel_launch(void* const* d_in, const int* in_sizes, int n_in,
                              void* d_out, int out_size)
{
    const float* q  = (const float*)d_in[0];
    const float* k  = (const float*)d_in[1];
    const float* v  = (const float*)d_in[2];
    const float* wq = (const float*)d_in[3];
    const float* wk = (const float*)d_in[4];
    const float* wv = (const float*)d_in[5];
    const float* wo = (const float*)d_in[6];
    float* out = (float*)d_out;

    float *xq, *xk, *xv, *xo, *wr;
    cudaGetSymbolAddress((void**)&xq, g_xq);
    cudaGetSymbolAddress((void**)&xk, g_xk);
    cudaGetSymbolAddress((void**)&xv, g_xv);
    cudaGetSymbolAddress((void**)&xo, g_xo);
    cudaGetSymbolAddress((void**)&wr, g_wr);

    cudaFuncSetAttribute(gemm_tc<1, 1>,
                         cudaFuncAttributeMaxDynamicSharedMemorySize, GEMM_SMEM);
    cudaFuncSetAttribute(gemm_tc<0, 0>,
                         cudaFuncAttributeMaxDynamicSharedMemorySize, GEMM_SMEM);
    cudaFuncSetAttribute(flash_tc,
                         cudaFuncAttributeMaxDynamicSharedMemorySize, FLASH_SMEM);

    // Pre-round weights to tf32
    dim3 rw_grid(DIM * DIM / 4 / 256, 4);
    round_w<<<rw_grid, 256>>>((const float4*)wq, (const float4*)wk,
                              (const float4*)wv, (const float4*)wo,
                              (float4*)wr);

    const float* wqr = wr;
    const float* wkr = wr + (size_t)DIM * DIM;
    const float* wvr = wr + (size_t)2 * DIM * DIM;
    const float* wor = wr + (size_t)3 * DIM * DIM;

    // Fused QKV projections (A-side cvt, rounded outputs)
    dim3 qkv_grid(DIM / 128, MTOT / 128, 3);   // (8, 32, 3)
    gemm_tc<1, 1><<<qkv_grid, 128, GEMM_SMEM>>>(q, k, v, wqr, wkr, wvr,
                                                xq, xk, xv, MTOT, DIM, DIM);

    dim3 flash_grid(SEQ / FQ, BATCH * NH);     // (16, 32)
    flash_tc<<<flash_grid, 256, FLASH_SMEM>>>(xq, xk, xv, xo);

    // O projection (inputs already tf32-rounded; full fp32 output)
    dim3 o_grid(DIM / 128, MTOT / 128, 1);     // (8, 32)
    gemm_tc<0, 0><<<o_grid, 128, GEMM_SMEM>>>(xo, xo, xo, wor, wor, wor,
                                              out, out, out, MTOT, DIM, DIM);
}

// round 14
// speedup vs baseline: 1.0005x; 1.0005x over previous
#include <cuda_runtime.h>
#include <math.h>

#define DIM 1024
#define NH 16
#define HD 64
#define BATCH 2
#define SEQ 2048
#define MTOT (BATCH * SEQ)   // 4096

// Scratch (device globals: allowed; no runtime allocation)
__device__ float g_xq[MTOT * DIM];
__device__ float g_xk[MTOT * DIM];
__device__ float g_xv[MTOT * DIM];
__device__ float g_xo[MTOT * DIM];
__device__ float g_wr[4 * DIM * DIM];   // tf32-rounded weights (wq,wk,wv,wo)

__device__ __forceinline__ unsigned f2tf(float x) {
    unsigned r;
    asm("cvt.rna.tf32.f32 %0, %1;" : "=r"(r) : "f"(x));
    return r;
}

__device__ __forceinline__ void mma_tf32(float* c, const unsigned* a, const unsigned* b) {
    asm volatile(
        "mma.sync.aligned.m16n8k8.row.col.f32.tf32.tf32.f32 "
        "{%0,%1,%2,%3}, {%4,%5,%6,%7}, {%8,%9}, {%0,%1,%2,%3};\n"
        : "+f"(c[0]), "+f"(c[1]), "+f"(c[2]), "+f"(c[3])
        : "r"(a[0]), "r"(a[1]), "r"(a[2]), "r"(a[3]), "r"(b[0]), "r"(b[1]));
}

__device__ __forceinline__ void ldsm_x4(unsigned& r0, unsigned& r1,
                                        unsigned& r2, unsigned& r3, unsigned addr) {
    asm volatile("ldmatrix.sync.aligned.m8n8.x4.shared.b16 {%0,%1,%2,%3}, [%4];"
                 : "=r"(r0), "=r"(r1), "=r"(r2), "=r"(r3) : "r"(addr));
}

__device__ __forceinline__ void cp_async16(void* smem_dst, const void* gptr) {
    unsigned s = (unsigned)__cvta_generic_to_shared(smem_dst);
    asm volatile("cp.async.cg.shared.global [%0], [%1], 16;\n" :: "r"(s), "l"(gptr));
}
__device__ __forceinline__ void cp_commit() {
    asm volatile("cp.async.commit_group;\n");
}
__device__ __forceinline__ void cp_wait0() { asm volatile("cp.async.wait_group 0;\n"); }
__device__ __forceinline__ void cp_wait1() { asm volatile("cp.async.wait_group 1;\n"); }
__device__ __forceinline__ void cp_wait2() { asm volatile("cp.async.wait_group 2;\n"); }

// ---------------------------------------------------------------------------
// Pre-round weights to tf32.
// ---------------------------------------------------------------------------
__global__ void __launch_bounds__(256) round_w(
    const float4* __restrict__ w0, const float4* __restrict__ w1,
    const float4* __restrict__ w2, const float4* __restrict__ w3,
    float4* __restrict__ dst)
{
    const int y = blockIdx.y;
    const float4* src = (y == 0) ? w0 : (y == 1) ? w1 : (y == 2) ? w2 : w3;
    const int i = blockIdx.x * 256 + threadIdx.x;
    float4 v = src[i];
    float4 r;
    r.x = __uint_as_float(f2tf(v.x));
    r.y = __uint_as_float(f2tf(v.y));
    r.z = __uint_as_float(f2tf(v.z));
    r.w = __uint_as_float(f2tf(v.w));
    dst[(size_t)y * (DIM * DIM / 4) + i] = r;
}

// ---------------------------------------------------------------------------
// TF32 NT GEMM (unchanged from R9): CTA 128x128, 128 threads, 3-stage
// cp.async, register fragment double-buffering, 2 CTAs/SM.
// ---------------------------------------------------------------------------
#define GLD 36
#define STG ((128 + 128) * GLD)
#define GEMM_SMEM (3 * STG * 4)   // 110592 bytes

template <int CVT_A, int ROUND_OUT>
__global__ void __launch_bounds__(128, 2) gemm_tc(
    const float* __restrict__ A0, const float* __restrict__ A1, const float* __restrict__ A2,
    const float* __restrict__ W0, const float* __restrict__ W1, const float* __restrict__ W2,
    float* __restrict__ C0, float* __restrict__ C1, float* __restrict__ C2,
    int M, int N, int K)
{
    extern __shared__ float smg[];
    const int z = blockIdx.z;
    const float* A = (z == 0) ? A0 : (z == 1) ? A1 : A2;
    const float* W = (z == 0) ? W0 : (z == 1) ? W1 : W2;
    float* C = (z == 0) ? C0 : (z == 1) ? C1 : C2;

    const int tid = threadIdx.x;
    const int warp = tid >> 5, lane = tid & 31;
    const int g = lane >> 2, t = lane & 3;
    const int lm = lane >> 3, lr8 = lane & 7;
    const int wm = (warp & 1) * 64;
    const int wn = (warp >> 1) * 64;
    const int bm = blockIdx.y * 128, bn = blockIdx.x * 128;

    const unsigned smem_u = (unsigned)__cvta_generic_to_shared(smg);
    const unsigned aoff = ((wm + (lm & 1) * 8 + lr8) * GLD + (lm >> 1) * 4) * 4;
    const unsigned boff = ((wn + (lm >> 1) * 8 + lr8) * GLD + (lm & 1) * 4) * 4;

    float acc[4][8][4] = {};

    auto load_stage = [&](int s) {
        float* As = smg + (s % 3) * STG;
        float* Bs = As + 128 * GLD;
        const int k0 = s * 32;
#pragma unroll
        for (int j = 0; j < 8; j++) {
            const int cid = tid + j * 128;
            const int row = cid >> 3, c4 = (cid & 7) * 4;
            cp_async16(As + row * GLD + c4, A + (size_t)(bm + row) * K + k0 + c4);
        }
#pragma unroll
        for (int j = 0; j < 8; j++) {
            const int cid = tid + j * 128;
            const int row = cid >> 3, c4 = (cid & 7) * 4;
            cp_async16(Bs + row * GLD + c4, W + (size_t)(bn + row) * K + k0 + c4);
        }
        cp_commit();
    };

    load_stage(0);
    load_stage(1);

    unsigned afr[2][4][4], bfr[2][8][2];

    const int niter = K / 32;
#pragma unroll 1
    for (int it = 0; it < niter; it++) {
        if (it + 1 < niter) cp_wait1(); else cp_wait0();
        __syncthreads();
        if (it + 2 < niter) load_stage(it + 2);

        const unsigned Ab = smem_u + (it % 3) * STG * 4 + aoff;
        const unsigned Bb = smem_u + ((it % 3) * STG + 128 * GLD) * 4 + boff;

#pragma unroll
        for (int mt = 0; mt < 4; mt++) {
            ldsm_x4(afr[0][mt][0], afr[0][mt][1], afr[0][mt][2], afr[0][mt][3],
                    Ab + (mt * 16 * GLD) * 4);
            if (CVT_A) {
#pragma unroll
                for (int r = 0; r < 4; r++)
                    afr[0][mt][r] = f2tf(__uint_as_float(afr[0][mt][r]));
            }
        }
#pragma unroll
        for (int ntp = 0; ntp < 4; ntp++)
            ldsm_x4(bfr[0][2 * ntp][0], bfr[0][2 * ntp][1],
                    bfr[0][2 * ntp + 1][0], bfr[0][2 * ntp + 1][1],
                    Bb + (ntp * 16 * GLD) * 4);

#pragma unroll
        for (int ks = 0; ks < 4; ks++) {
            const int cur = ks & 1, nxt = cur ^ 1;
            if (ks < 3) {
#pragma unroll
                for (int mt = 0; mt < 4; mt++) {
                    ldsm_x4(afr[nxt][mt][0], afr[nxt][mt][1],
                            afr[nxt][mt][2], afr[nxt][mt][3],
                            Ab + (mt * 16 * GLD + (ks + 1) * 8) * 4);
                    if (CVT_A) {
#pragma unroll
                        for (int r = 0; r < 4; r++)
                            afr[nxt][mt][r] = f2tf(__uint_as_float(afr[nxt][mt][r]));
                    }
                }
#pragma unroll
                for (int ntp = 0; ntp < 4; ntp++)
                    ldsm_x4(bfr[nxt][2 * ntp][0], bfr[nxt][2 * ntp][1],
                            bfr[nxt][2 * ntp + 1][0], bfr[nxt][2 * ntp + 1][1],
                            Bb + (ntp * 16 * GLD + (ks + 1) * 8) * 4);
            }
#pragma unroll
            for (int mt = 0; mt < 4; mt++)
#pragma unroll
                for (int nt = 0; nt < 8; nt++)
                    mma_tf32(acc[mt][nt], afr[cur][mt], bfr[cur][nt]);
        }
    }

#pragma unroll
    for (int mt = 0; mt < 4; mt++)
#pragma unroll
        for (int nt = 0; nt < 8; nt++) {
            const int row = bm + wm + mt * 16 + g;
            const int col = bn + wn + nt * 8 + 2 * t;
            float v0 = acc[mt][nt][0], v1 = acc[mt][nt][1];
            float v2 = acc[mt][nt][2], v3 = acc[mt][nt][3];
            if (ROUND_OUT) {
                v0 = __uint_as_float(f2tf(v0)); v1 = __uint_as_float(f2tf(v1));
                v2 = __uint_as_float(f2tf(v2)); v3 = __uint_as_float(f2tf(v3));
            }
            *(float2*)&C[(size_t)row * N + col] = make_float2(v0, v1);
            *(float2*)&C[(size_t)(row + 8) * N + col] = make_float2(v2, v3);
        }
}

// ---------------------------------------------------------------------------
// TF32 flash attention, SOFTWARE-PIPELINED: S(kt+1) MMAs are issued inside
// iteration kt, between the softmax max/alpha chain and the exp/PV section,
// filling the softmax latency shadow with tensor work.
// FQ=128 (8 warps x 16 rows), KV tiles 64, 4-stage cp.async K/V ring.
// ---------------------------------------------------------------------------
#define FQ 128
#define FK 64
#define LDK 68
#define LDV 72
#define LDP 68
#define KBUF (FK * LDK)
#define VBUF (FK * LDV)
#define FLASH_SMEM ((4 * KBUF + 4 * VBUF + FQ * LDP) * 4)   // 178176 bytes

__global__ void __launch_bounds__(256, 1) flash_tc(
    const float* __restrict__ xq, const float* __restrict__ xk,
    const float* __restrict__ xv, float* __restrict__ xo)
{
    extern __shared__ float smf[];
    float* Kst = smf;                    // 4 * KBUF
    float* Vst = Kst + 4 * KBUF;         // 4 * VBUF
    unsigned* Ps = (unsigned*)(Vst + 4 * VBUF);   // FQ * LDP

    const int tid = threadIdx.x;
    const int warp = tid >> 5, lane = tid & 31;
    const int g = lane >> 2, t = lane & 3;
    const int lm = lane >> 3, lr8 = lane & 7;
    const int qt = gridDim.x - 1 - blockIdx.x;   // big tiles first
    const int bh = blockIdx.y;
    const int b = bh >> 4, h = bh & 15;
    const size_t base = (size_t)b * SEQ * DIM + (size_t)h * HD;
    const int qrow0 = qt * FQ + warp * 16;

    const unsigned smem_u = (unsigned)__cvta_generic_to_shared(smf);
    const unsigned koff = (((lm >> 1) * 8 + lr8) * LDK + (lm & 1) * 4) * 4;
    const unsigned poff = (unsigned)((4 * KBUF + 4 * VBUF) * 4) +
        (((warp * 16 + (lm & 1) * 8 + lr8) * LDP + (lm >> 1) * 4) * 4);

    // K/V loads: 256 threads cover 64 rows x 64 cols
    const int lr = tid >> 2;             // kv row 0..63
    const int lc = (tid & 3) * 16;       // col base
    const float* kbase = xk + base + (size_t)lr * DIM + lc;
    const float* vbase = xv + base + (size_t)lr * DIM + lc;

    const int nkt = 2 * (qt + 1);

    auto load_kv = [&](int s) {
        float* kd = Kst + (s & 3) * KBUF + lr * LDK + lc;
        float* vd = Vst + (s & 3) * VBUF + lr * LDV + lc;
        const size_t off = (size_t)s * FK * DIM;
#pragma unroll
        for (int f = 0; f < 4; f++) {
            cp_async16(kd + f * 4, kbase + off + f * 4);
            cp_async16(vd + f * 4, vbase + off + f * 4);
        }
        cp_commit();
    };

    // Prologue: stages 0..min(2, nkt-1)
    load_kv(0);
    if (nkt > 1) load_kv(1);
    if (nkt > 2) load_kv(2);

    // Q fragments (pre-rounded tf32; *0.125 exact)
    unsigned qf[8][4];
    {
        const float* q0 = xq + base + (size_t)(qrow0 + g) * DIM;
        const float* q1 = xq + base + (size_t)(qrow0 + g + 8) * DIM;
#pragma unroll
        for (int c = 0; c < 8; c++) {
            qf[c][0] = __float_as_uint(q0[8 * c + t] * 0.125f);
            qf[c][1] = __float_as_uint(q1[8 * c + t] * 0.125f);
            qf[c][2] = __float_as_uint(q0[8 * c + t + 4] * 0.125f);
            qf[c][3] = __float_as_uint(q1[8 * c + t + 4] * 0.125f);
        }
    }

    // S-tile compute: sv must be zero-initialized by caller
    auto compute_S = [&](int kt, float (*sv)[4]) {
        const unsigned Kb = smem_u + (kt & 3) * KBUF * 4 + koff;
        unsigned bfr[2][8][2];
#pragma unroll
        for (int ntp = 0; ntp < 4; ntp++)
            ldsm_x4(bfr[0][2 * ntp][0], bfr[0][2 * ntp][1],
                    bfr[0][2 * ntp + 1][0], bfr[0][2 * ntp + 1][1],
                    Kb + (ntp * 16 * LDK) * 4);
#pragma unroll
        for (int c = 0; c < 8; c++) {
            const int cur = c & 1, nxt = cur ^ 1;
            if (c < 7) {
#pragma unroll
                for (int ntp = 0; ntp < 4; ntp++)
                    ldsm_x4(bfr[nxt][2 * ntp][0], bfr[nxt][2 * ntp][1],
                            bfr[nxt][2 * ntp + 1][0], bfr[nxt][2 * ntp + 1][1],
                            Kb + (ntp * 16 * LDK + (c + 1) * 8) * 4);
            }
#pragma unroll
            for (int nt = 0; nt < 8; nt++)
                mma_tf32(sv[nt], qf[c], bfr[cur][nt]);
        }
    };

    if (nkt > 2) cp_wait2(); else cp_wait1();
    __syncthreads();

    float s_cur[8][4] = {};
    compute_S(0, s_cur);

    float o[8][4] = {};
    float m0 = -1e30f, m1 = -1e30f, l0 = 0.f, l1 = 0.f;
    unsigned* Pw = Ps + (warp * 16) * LDP;

#pragma unroll 1
    for (int kt = 0; kt < nkt; kt++) {
        // Stage management: ensure stage kt+1 arrived; recycle buffer (kt+3)&3
        if (kt + 1 < nkt) {
            if (kt + 2 < nkt) cp_wait1(); else cp_wait0();
            __syncthreads();   // all warps done reading stages kt-1 (PV) / kt (S frags)
            if (kt + 3 < nkt) load_kv(kt + 3);
        }

        const bool act  = (kt * FK <= qrow0 + 15);
        const bool actn = (kt + 1 < nkt) && ((kt + 1) * FK <= qrow0 + 15);

        // ---- softmax part A: mask, max, alpha (latency chain) ----
        float mn0 = m0, mn1 = m1, al0 = 1.f, al1 = 1.f;
        if (act) {
            if (kt * FK + FK - 1 > qrow0) {
                const int rg0 = qrow0 + g, rg1 = qrow0 + g + 8;
#pragma unroll
                for (int nt = 0; nt < 8; nt++) {
                    const int col = kt * FK + nt * 8 + 2 * t;
                    if (col > rg0)     s_cur[nt][0] = -1e30f;
                    if (col + 1 > rg0) s_cur[nt][1] = -1e30f;
                    if (col > rg1)     s_cur[nt][2] = -1e30f;
                    if (col + 1 > rg1) s_cur[nt][3] = -1e30f;
                }
            }
            float mx0 = -1e30f, mx1 = -1e30f;
#pragma unroll
            for (int nt = 0; nt < 8; nt++) {
                mx0 = fmaxf(mx0, fmaxf(s_cur[nt][0], s_cur[nt][1]));
                mx1 = fmaxf(mx1, fmaxf(s_cur[nt][2], s_cur[nt][3]));
            }
            mx0 = fmaxf(mx0, __shfl_xor_sync(0xffffffffu, mx0, 1));
            mx0 = fmaxf(mx0, __shfl_xor_sync(0xffffffffu, mx0, 2));
            mx1 = fmaxf(mx1, __shfl_xor_sync(0xffffffffu, mx1, 1));
            mx1 = fmaxf(mx1, __shfl_xor_sync(0xffffffffu, mx1, 2));
            mn0 = fmaxf(m0, mx0);
            mn1 = fmaxf(m1, mx1);
            al0 = __expf(m0 - mn0);
            al1 = __expf(m1 - mn1);
            m0 = mn0; m1 = mn1;
        }

        // ---- S(kt+1): independent tensor work in the softmax shadow ----
        float s_nxt[8][4] = {};
        if (actn) compute_S(kt + 1, s_nxt);

        if (act) {
            // ---- softmax part B: exp, P store, row sums ----
            float sum0 = 0.f, sum1 = 0.f;
#pragma unroll
            for (int nt = 0; nt < 8; nt++) {
                float p0 = __expf(s_cur[nt][0] - mn0);
                float p1 = __expf(s_cur[nt][1] - mn0);
                float p2 = __expf(s_cur[nt][2] - mn1);
                float p3 = __expf(s_cur[nt][3] - mn1);
                sum0 += p0 + p1;
                sum1 += p2 + p3;
                unsigned* pr0 = Pw + g * LDP + nt * 8 + 2 * t;
                unsigned* pr1 = Pw + (g + 8) * LDP + nt * 8 + 2 * t;
                pr0[0] = f2tf(p0); pr0[1] = f2tf(p1);
                pr1[0] = f2tf(p2); pr1[1] = f2tf(p3);
            }
            sum0 += __shfl_xor_sync(0xffffffffu, sum0, 1);
            sum0 += __shfl_xor_sync(0xffffffffu, sum0, 2);
            sum1 += __shfl_xor_sync(0xffffffffu, sum1, 1);
            sum1 += __shfl_xor_sync(0xffffffffu, sum1, 2);
            l0 = l0 * al0 + sum0;
            l1 = l1 * al1 + sum1;

#pragma unroll
            for (int nt = 0; nt < 8; nt++) {
                o[nt][0] *= al0; o[nt][1] *= al0;
                o[nt][2] *= al1; o[nt][3] *= al1;
            }
            __syncwarp();

            // ---- O += P @ V ----
            const float* Vsf = Vst + (kt & 3) * VBUF;
#pragma unroll
            for (int c = 0; c < 8; c++) {
                unsigned pafr[4];
                ldsm_x4(pafr[0], pafr[1], pafr[2], pafr[3],
                        smem_u + poff + (c * 8) * 4);
#pragma unroll
                for (int nt = 0; nt < 8; nt++) {
                    unsigned bfr2[2];
                    bfr2[0] = __float_as_uint(Vsf[(c * 8 + t) * LDV + nt * 8 + g]);
                    bfr2[1] = __float_as_uint(Vsf[(c * 8 + t + 4) * LDV + nt * 8 + g]);
                    mma_tf32(o[nt], pafr, bfr2);
                }
            }
        }

        // Rotate pipeline register state
#pragma unroll
        for (int nt = 0; nt < 8; nt++) {
            s_cur[nt][0] = s_nxt[nt][0];
            s_cur[nt][1] = s_nxt[nt][1];
            s_cur[nt][2] = s_nxt[nt][2];
            s_cur[nt][3] = s_nxt[nt][3];
        }
    }

    // Normalize and write (tf32-rounded for the O-projection GEMM)
    const float inv0 = 1.f / l0, inv1 = 1.f / l1;
#pragma unroll
    for (int nt = 0; nt < 8; nt++) {
        const int col = nt * 8 + 2 * t;
        float* d0 = xo + base + (size_t)(qrow0 + g) * DIM + col;
        float* d1 = xo + base + (size_t)(qrow0 + g + 8) * DIM + col;
        *(float2*)d0 = make_float2(__uint_as_float(f2tf(o[nt][0] * inv0)),
                                   __uint_as_float(f2tf(o[nt][1] * inv0)));
        *(float2*)d1 = make_float2(__uint_as_float(f2tf(o[nt][2] * inv1)),
                                   __uint_as_float(f2tf(o[nt][3] * inv1)));
    }
}

// ---------------------------------------------------------------------------
// Launch
// ---------------------------------------------------------------------------
extern "C" void kernel_launch(void* const* d_in, const int* in_sizes, int n_in,
                              void* d_out, int out_size)
{
    const float* q  = (const float*)d_in[0];
    const float* k  = (const float*)d_in[1];
    const float* v  = (const float*)d_in[2];
    const float* wq = (const float*)d_in[3];
    const float* wk = (const float*)d_in[4];
    const float* wv = (const float*)d_in[5];
    const float* wo = (const float*)d_in[6];
    float* out = (float*)d_out;

    float *xq, *xk, *xv, *xo, *wr;
    cudaGetSymbolAddress((void**)&xq, g_xq);
    cudaGetSymbolAddress((void**)&xk, g_xk);
    cudaGetSymbolAddress((void**)&xv, g_xv);
    cudaGetSymbolAddress((void**)&xo, g_xo);
    cudaGetSymbolAddress((void**)&wr, g_wr);

    cudaFuncSetAttribute(gemm_tc<1, 1>,
                         cudaFuncAttributeMaxDynamicSharedMemorySize, GEMM_SMEM);
    cudaFuncSetAttribute(gemm_tc<0, 0>,
                         cudaFuncAttributeMaxDynamicSharedMemorySize, GEMM_SMEM);
    cudaFuncSetAttribute(flash_tc,
                         cudaFuncAttributeMaxDynamicSharedMemorySize, FLASH_SMEM);

    // Pre-round weights to tf32
    dim3 rw_grid(DIM * DIM / 4 / 256, 4);
    round_w<<<rw_grid, 256>>>((const float4*)wq, (const float4*)wk,
                              (const float4*)wv, (const float4*)wo,
                              (float4*)wr);

    const float* wqr = wr;
    const float* wkr = wr + (size_t)DIM * DIM;
    const float* wvr = wr + (size_t)2 * DIM * DIM;
    const float* wor = wr + (size_t)3 * DIM * DIM;

    // Fused QKV projections (A-side cvt, rounded outputs)
    dim3 qkv_grid(DIM / 128, MTOT / 128, 3);   // (8, 32, 3)
    gemm_tc<1, 1><<<qkv_grid, 128, GEMM_SMEM>>>(q, k, v, wqr, wkr, wvr,
                                                xq, xk, xv, MTOT, DIM, DIM);

    dim3 flash_grid(SEQ / FQ, BATCH * NH);     // (16, 32)
    flash_tc<<<flash_grid, 256, FLASH_SMEM>>>(xq, xk, xv, xo);

    // O projection (inputs already tf32-rounded; full fp32 output)
    dim3 o_grid(DIM / 128, MTOT / 128, 1);     // (8, 32)
    gemm_tc<0, 0><<<o_grid, 128, GEMM_SMEM>>>(xo, xo, xo, wor, wor, wor,
                                              out, out, out, MTOT, DIM, DIM);
}

// round 15
// speedup vs baseline: 1.7895x; 1.7886x over previous
#include <cuda_runtime.h>
#include <cuda_fp16.h>
#include <math.h>

#define DIM 1024
#define NH 16
#define HD 64
#define BATCH 2
#define SEQ 2048
#define MTOT (BATCH * SEQ)   // 4096

// Scratch (device globals: allowed; no runtime allocation)
__device__ __half g_wh[4 * DIM * DIM];    // fp16 weights (wq,wk,wv,wo)
__device__ __half g_qh[MTOT * DIM];       // fp16 inputs
__device__ __half g_kh[MTOT * DIM];
__device__ __half g_vh[MTOT * DIM];
__device__ __half g_xqh[MTOT * DIM];      // fp16 projections
__device__ __half g_xkh[MTOT * DIM];
__device__ __half g_xvh[MTOT * DIM];
__device__ __half g_xoh[MTOT * DIM];      // fp16 attention output

__device__ __forceinline__ void mma_f16(float* c, const unsigned* a, const unsigned* b) {
    asm volatile(
        "mma.sync.aligned.m16n8k16.row.col.f32.f16.f16.f32 "
        "{%0,%1,%2,%3}, {%4,%5,%6,%7}, {%8,%9}, {%0,%1,%2,%3};\n"
        : "+f"(c[0]), "+f"(c[1]), "+f"(c[2]), "+f"(c[3])
        : "r"(a[0]), "r"(a[1]), "r"(a[2]), "r"(a[3]), "r"(b[0]), "r"(b[1]));
}

__device__ __forceinline__ void ldsm_x4(unsigned& r0, unsigned& r1,
                                        unsigned& r2, unsigned& r3, unsigned addr) {
    asm volatile("ldmatrix.sync.aligned.m8n8.x4.shared.b16 {%0,%1,%2,%3}, [%4];"
                 : "=r"(r0), "=r"(r1), "=r"(r2), "=r"(r3) : "r"(addr));
}
__device__ __forceinline__ void ldsm_x4_t(unsigned& r0, unsigned& r1,
                                          unsigned& r2, unsigned& r3, unsigned addr) {
    asm volatile("ldmatrix.sync.aligned.m8n8.x4.trans.shared.b16 {%0,%1,%2,%3}, [%4];"
                 : "=r"(r0), "=r"(r1), "=r"(r2), "=r"(r3) : "r"(addr));
}

__device__ __forceinline__ void cp_async16(void* smem_dst, const void* gptr) {
    unsigned s = (unsigned)__cvta_generic_to_shared(smem_dst);
    asm volatile("cp.async.cg.shared.global [%0], [%1], 16;\n" :: "r"(s), "l"(gptr));
}
__device__ __forceinline__ void cp_commit() {
    asm volatile("cp.async.commit_group;\n");
}
__device__ __forceinline__ void cp_wait0() { asm volatile("cp.async.wait_group 0;\n"); }
__device__ __forceinline__ void cp_wait1() { asm volatile("cp.async.wait_group 1;\n"); }

// ---------------------------------------------------------------------------
// fp32 -> fp16 conversion passes
// ---------------------------------------------------------------------------
__global__ void __launch_bounds__(256) cvt_w4(
    const float4* __restrict__ w0, const float4* __restrict__ w1,
    const float4* __restrict__ w2, const float4* __restrict__ w3,
    __half2* __restrict__ dst, int n4)
{
    const int y = blockIdx.y;
    const float4* src = (y == 0) ? w0 : (y == 1) ? w1 : (y == 2) ? w2 : w3;
    const int i = blockIdx.x * 256 + threadIdx.x;
    float4 v = src[i];
    __half2* d = dst + (size_t)y * n4 * 2;
    d[2 * i]     = __floats2half2_rn(v.x, v.y);
    d[2 * i + 1] = __floats2half2_rn(v.z, v.w);
}

__global__ void __launch_bounds__(256) cvt_in3(
    const float4* __restrict__ s0, const float4* __restrict__ s1,
    const float4* __restrict__ s2,
    __half2* __restrict__ d0, __half2* __restrict__ d1, __half2* __restrict__ d2)
{
    const int y = blockIdx.y;
    const float4* src = (y == 0) ? s0 : (y == 1) ? s1 : s2;
    __half2* d = (y == 0) ? d0 : (y == 1) ? d1 : d2;
    const int i = blockIdx.x * 256 + threadIdx.x;
    float4 v = src[i];
    d[2 * i]     = __floats2half2_rn(v.x, v.y);
    d[2 * i + 1] = __floats2half2_rn(v.z, v.w);
}

// ---------------------------------------------------------------------------
// FP16 NT GEMM: C[M,N] = A[M,K] @ W[N,K]^T, fp32 accumulate.
// CTA 128x128, 128 threads (4 warps of 64x64), BK=32 halves, 3-stage cp.async,
// fragment double-buffering across the 2 k-steps, 2 CTAs/SM.
// LDH=40 halves (80B rows): ldmatrix row addrs 5r mod 8 -> conflict-free.
// OUT_HALF: 1 -> writes __half (scaled by sc), 0 -> writes float.
// ---------------------------------------------------------------------------
#define LDH 40
#define STGH ((128 + 128) * LDH)          // halves per stage
#define GEMM_SMEM (3 * STGH * 2)          // 61440 bytes

template <int OUT_HALF>
__global__ void __launch_bounds__(128, 2) gemm_h(
    const __half* __restrict__ A0, const __half* __restrict__ A1, const __half* __restrict__ A2,
    const __half* __restrict__ W0, const __half* __restrict__ W1, const __half* __restrict__ W2,
    void* __restrict__ C0, void* __restrict__ C1, void* __restrict__ C2,
    float s0, float s1, float s2, int M, int N, int K)
{
    extern __shared__ __half smh[];
    const int z = blockIdx.z;
    const __half* A = (z == 0) ? A0 : (z == 1) ? A1 : A2;
    const __half* W = (z == 0) ? W0 : (z == 1) ? W1 : W2;
    void* Cv = (z == 0) ? C0 : (z == 1) ? C1 : C2;
    const float sc = (z == 0) ? s0 : (z == 1) ? s1 : s2;

    const int tid = threadIdx.x;
    const int warp = tid >> 5, lane = tid & 31;
    const int g = lane >> 2, t = lane & 3;
    const int lm = lane >> 3, lr8 = lane & 7;
    const int wm = (warp & 1) * 64;
    const int wn = (warp >> 1) * 64;
    const int bm = blockIdx.y * 128, bn = blockIdx.x * 128;

    const unsigned smem_u = (unsigned)__cvta_generic_to_shared(smh);
    // A frag: matrices (rows0-7,k0),(rows8-15,k0),(rows0-7,k8),(rows8-15,k8)
    const unsigned aoff = ((wm + (lm & 1) * 8 + lr8) * LDH + (lm >> 1) * 8) * 2;
    // B frag: matrices (n-pair rows0-7,k0),(rows0-7,k8),(rows8-15,k0),(rows8-15,k8)
    const unsigned boff = ((wn + (lm >> 1) * 8 + lr8) * LDH + (lm & 1) * 8) * 2;

    float acc[4][8][4] = {};

    auto load_stage = [&](int s) {
        __half* As = smh + (s % 3) * STGH;
        __half* Bs = As + 128 * LDH;
        const int k0 = s * 32;
#pragma unroll
        for (int j = 0; j < 4; j++) {
            const int cid = tid + j * 128;
            const int row = cid >> 2, c16 = cid & 3;
            cp_async16(As + row * LDH + c16 * 8, A + (size_t)(bm + row) * K + k0 + c16 * 8);
            cp_async16(Bs + row * LDH + c16 * 8, W + (size_t)(bn + row) * K + k0 + c16 * 8);
        }
        cp_commit();
    };

    load_stage(0);
    load_stage(1);

    unsigned afr[2][4][4], bfr[2][8][2];

    const int niter = K / 32;   // 32
#pragma unroll 1
    for (int it = 0; it < niter; it++) {
        if (it + 1 < niter) cp_wait1(); else cp_wait0();
        __syncthreads();
        if (it + 2 < niter) load_stage(it + 2);

        const unsigned Ab = smem_u + (it % 3) * STGH * 2 + aoff;
        const unsigned Bb = smem_u + ((it % 3) * STGH + 128 * LDH) * 2 + boff;

        // ks=0 fragments
#pragma unroll
        for (int mt = 0; mt < 4; mt++)
            ldsm_x4(afr[0][mt][0], afr[0][mt][1], afr[0][mt][2], afr[0][mt][3],
                    Ab + (mt * 16 * LDH) * 2);
#pragma unroll
        for (int p = 0; p < 4; p++)
            ldsm_x4(bfr[0][2 * p][0], bfr[0][2 * p][1],
                    bfr[0][2 * p + 1][0], bfr[0][2 * p + 1][1],
                    Bb + (p * 16 * LDH) * 2);

#pragma unroll
        for (int ks = 0; ks < 2; ks++) {
            const int cur = ks & 1, nxt = cur ^ 1;
            if (ks == 0) {
                // prefetch ks=1 fragments (k offset 16 halves)
#pragma unroll
                for (int mt = 0; mt < 4; mt++)
                    ldsm_x4(afr[nxt][mt][0], afr[nxt][mt][1],
                            afr[nxt][mt][2], afr[nxt][mt][3],
                            Ab + (mt * 16 * LDH + 16) * 2);
#pragma unroll
                for (int p = 0; p < 4; p++)
                    ldsm_x4(bfr[nxt][2 * p][0], bfr[nxt][2 * p][1],
                            bfr[nxt][2 * p + 1][0], bfr[nxt][2 * p + 1][1],
                            Bb + (p * 16 * LDH + 16) * 2);
            }
#pragma unroll
            for (int mt = 0; mt < 4; mt++)
#pragma unroll
                for (int nt = 0; nt < 8; nt++)
                    mma_f16(acc[mt][nt], afr[cur][mt], bfr[cur][nt]);
        }
    }

#pragma unroll
    for (int mt = 0; mt < 4; mt++)
#pragma unroll
        for (int nt = 0; nt < 8; nt++) {
            const int row = bm + wm + mt * 16 + g;
            const int col = bn + wn + nt * 8 + 2 * t;
            const float v0 = acc[mt][nt][0] * sc, v1 = acc[mt][nt][1] * sc;
            const float v2 = acc[mt][nt][2] * sc, v3 = acc[mt][nt][3] * sc;
            if (OUT_HALF) {
                __half* C = (__half*)Cv;
                *(__half2*)&C[(size_t)row * N + col] = __floats2half2_rn(v0, v1);
                *(__half2*)&C[(size_t)(row + 8) * N + col] = __floats2half2_rn(v2, v3);
            } else {
                float* C = (float*)Cv;
                *(float2*)&C[(size_t)row * N + col] = make_float2(v0, v1);
                *(float2*)&C[(size_t)(row + 8) * N + col] = make_float2(v2, v3);
            }
        }
}

// ---------------------------------------------------------------------------
// FP16 flash attention: FQ=128 (8 warps x 16 rows), KV tiles 64, fp32 softmax
// and O accumulation. K/V cp.async double-buffered. V fragments via
// ldmatrix.x4.trans straight from the natural kv x d layout. 2 CTAs/SM.
// xq is pre-scaled by 1/8 (folded into the QKV GEMM epilogue).
// ---------------------------------------------------------------------------
#define FQ 128
#define FK 64
#define LDKH 72
#define LDVH 72
#define LDPH 72
#define KBUFH (FK * LDKH)
#define VBUFH (FK * LDVH)
#define FLASH_SMEM ((2 * KBUFH + 2 * VBUFH + FQ * LDPH) * 2)   // 55296 bytes

__global__ void __launch_bounds__(256, 2) flash_h(
    const __half* __restrict__ xq, const __half* __restrict__ xk,
    const __half* __restrict__ xv, __half* __restrict__ xo)
{
    extern __shared__ __half smh[];
    __half* Kst = smh;                    // 2 * KBUFH
    __half* Vst = Kst + 2 * KBUFH;        // 2 * VBUFH
    __half* Ps  = Vst + 2 * VBUFH;        // FQ * LDPH

    const int tid = threadIdx.x;
    const int warp = tid >> 5, lane = tid & 31;
    const int g = lane >> 2, t = lane & 3;
    const int lm = lane >> 3, lr8 = lane & 7;
    const int qt = gridDim.x - 1 - blockIdx.x;   // big tiles first
    const int bh = blockIdx.y;
    const int b = bh >> 4, h = bh & 15;
    const size_t base = (size_t)b * SEQ * DIM + (size_t)h * HD;
    const int qrow0 = qt * FQ + warp * 16;

    const unsigned smem_u = (unsigned)__cvta_generic_to_shared(smh);
    const unsigned koff = (((lm >> 1) * 8 + lr8) * LDKH + (lm & 1) * 8) * 2;
    const unsigned voff = (unsigned)(2 * KBUFH * 2) +
        (((lm & 1) * 8 + lr8) * LDVH + (lm >> 1) * 8) * 2;
    const unsigned poff = (unsigned)((2 * KBUFH + 2 * VBUFH) * 2) +
        ((warp * 16 + (lm & 1) * 8 + lr8) * LDPH + (lm >> 1) * 8) * 2;

    const __half* kbase = xk + base;
    const __half* vbase = xv + base;
    const int nkt = 2 * (qt + 1);

    auto load_kv = [&](int s) {
        __half* kd = Kst + (s & 1) * KBUFH;
        __half* vd = Vst + (s & 1) * VBUFH;
#pragma unroll
        for (int j = 0; j < 2; j++) {
            const int cid = tid + j * 256;
            const int row = cid >> 3, c16 = cid & 7;
            const size_t go = (size_t)(s * FK + row) * DIM + c16 * 8;
            cp_async16(kd + row * LDKH + c16 * 8, kbase + go);
            cp_async16(vd + row * LDVH + c16 * 8, vbase + go);
        }
        cp_commit();
    };

    load_kv(0);

    // Q fragments: 4 k16 steps, direct u32 loads (xq pre-scaled by 1/8)
    unsigned qf[4][4];
    {
        const __half* q0 = xq + base + (size_t)(qrow0 + g) * DIM;
        const __half* q1 = q0 + (size_t)8 * DIM;
#pragma unroll
        for (int c = 0; c < 4; c++) {
            qf[c][0] = *(const unsigned*)(q0 + c * 16 + 2 * t);
            qf[c][1] = *(const unsigned*)(q1 + c * 16 + 2 * t);
            qf[c][2] = *(const unsigned*)(q0 + c * 16 + 2 * t + 8);
            qf[c][3] = *(const unsigned*)(q1 + c * 16 + 2 * t + 8);
        }
    }

    float o[8][4] = {};
    float m0 = -1e30f, m1 = -1e30f, l0 = 0.f, l1 = 0.f;
    __half* Pwh = Ps + warp * 16 * LDPH;

#pragma unroll 1
    for (int kt = 0; kt < nkt; kt++) {
        cp_wait0();
        __syncthreads();   // tile kt ready; all warps done with tile kt-1

        if (kt + 1 < nkt) load_kv(kt + 1);

        if (kt * FK > qrow0 + 15) continue;   // fully masked for this warp

        const unsigned Kb = smem_u + (kt & 1) * KBUFH * 2 + koff;

        // S = Q @ K^T  (fp32 accum)
        float s[8][4] = {};
#pragma unroll
        for (int c = 0; c < 4; c++) {
            unsigned bfr[8][2];
#pragma unroll
            for (int p = 0; p < 4; p++)
                ldsm_x4(bfr[2 * p][0], bfr[2 * p][1],
                        bfr[2 * p + 1][0], bfr[2 * p + 1][1],
                        Kb + (p * 16 * LDKH + c * 16) * 2);
#pragma unroll
            for (int nt = 0; nt < 8; nt++)
                mma_f16(s[nt], qf[c], bfr[nt]);
        }

        // Causal mask (tiles straddling the diagonal)
        if (kt * FK + FK - 1 > qrow0) {
            const int rg0 = qrow0 + g, rg1 = qrow0 + g + 8;
#pragma unroll
            for (int nt = 0; nt < 8; nt++) {
                const int col = kt * FK + nt * 8 + 2 * t;
                if (col > rg0)     s[nt][0] = -1e30f;
                if (col + 1 > rg0) s[nt][1] = -1e30f;
                if (col > rg1)     s[nt][2] = -1e30f;
                if (col + 1 > rg1) s[nt][3] = -1e30f;
            }
        }

        // Online softmax (fp32)
        float mx0 = -1e30f, mx1 = -1e30f;
#pragma unroll
        for (int nt = 0; nt < 8; nt++) {
            mx0 = fmaxf(mx0, fmaxf(s[nt][0], s[nt][1]));
            mx1 = fmaxf(mx1, fmaxf(s[nt][2], s[nt][3]));
        }
        mx0 = fmaxf(mx0, __shfl_xor_sync(0xffffffffu, mx0, 1));
        mx0 = fmaxf(mx0, __shfl_xor_sync(0xffffffffu, mx0, 2));
        mx1 = fmaxf(mx1, __shfl_xor_sync(0xffffffffu, mx1, 1));
        mx1 = fmaxf(mx1, __shfl_xor_sync(0xffffffffu, mx1, 2));

        const float mn0 = fmaxf(m0, mx0);
        const float mn1 = fmaxf(m1, mx1);
        const float al0 = __expf(m0 - mn0);
        const float al1 = __expf(m1 - mn1);
        m0 = mn0; m1 = mn1;

        float sum0 = 0.f, sum1 = 0.f;
#pragma unroll
        for (int nt = 0; nt < 8; nt++) {
            const float p0 = __expf(s[nt][0] - mn0);
            const float p1 = __expf(s[nt][1] - mn0);
            const float p2 = __expf(s[nt][2] - mn1);
            const float p3 = __expf(s[nt][3] - mn1);
            sum0 += p0 + p1;
            sum1 += p2 + p3;
            *(__half2*)(Pwh + g * LDPH + nt * 8 + 2 * t) = __floats2half2_rn(p0, p1);
            *(__half2*)(Pwh + (g + 8) * LDPH + nt * 8 + 2 * t) = __floats2half2_rn(p2, p3);
        }
        sum0 += __shfl_xor_sync(0xffffffffu, sum0, 1);
        sum0 += __shfl_xor_sync(0xffffffffu, sum0, 2);
        sum1 += __shfl_xor_sync(0xffffffffu, sum1, 1);
        sum1 += __shfl_xor_sync(0xffffffffu, sum1, 2);
        l0 = l0 * al0 + sum0;
        l1 = l1 * al1 + sum1;

#pragma unroll
        for (int nt = 0; nt < 8; nt++) {
            o[nt][0] *= al0; o[nt][1] *= al0;
            o[nt][2] *= al1; o[nt][3] *= al1;
        }
        __syncwarp();

        // O += P @ V   (V frags via ldmatrix.trans from natural kv x d layout)
        const unsigned Vb = smem_u + voff + (kt & 1) * VBUFH * 2;
#pragma unroll
        for (int c = 0; c < 4; c++) {
            unsigned pafr[4];
            ldsm_x4(pafr[0], pafr[1], pafr[2], pafr[3],
                    smem_u + poff + (c * 16) * 2);
            unsigned vfr[8][2];
#pragma unroll
            for (int p = 0; p < 4; p++)
                ldsm_x4_t(vfr[2 * p][0], vfr[2 * p][1],
                          vfr[2 * p + 1][0], vfr[2 * p + 1][1],
                          Vb + (c * 16 * LDVH + p * 16) * 2);
#pragma unroll
            for (int nt = 0; nt < 8; nt++)
                mma_f16(o[nt], pafr, vfr[nt]);
        }
    }

    // Normalize and write (fp16 for the O-projection GEMM)
    const float inv0 = 1.f / l0, inv1 = 1.f / l1;
    __half* d0 = xo + base + (size_t)(qrow0 + g) * DIM;
    __half* d1 = d0 + (size_t)8 * DIM;
#pragma unroll
    for (int nt = 0; nt < 8; nt++) {
        const int col = nt * 8 + 2 * t;
        *(__half2*)(d0 + col) = __floats2half2_rn(o[nt][0] * inv0, o[nt][1] * inv0);
        *(__half2*)(d1 + col) = __floats2half2_rn(o[nt][2] * inv1, o[nt][3] * inv1);
    }
}

// ---------------------------------------------------------------------------
// Launch
// ---------------------------------------------------------------------------
extern "C" void kernel_launch(void* const* d_in, const int* in_sizes, int n_in,
                              void* d_out, int out_size)
{
    const float* q  = (const float*)d_in[0];
    const float* k  = (const float*)d_in[1];
    const float* v  = (const float*)d_in[2];
    const float* wq = (const float*)d_in[3];
    const float* wk = (const float*)d_in[4];
    const float* wv = (const float*)d_in[5];
    const float* wo = (const float*)d_in[6];
    float* out = (float*)d_out;

    __half *wh, *qh, *kh, *vh, *xqh, *xkh, *xvh, *xoh;
    cudaGetSymbolAddress((void**)&wh,  g_wh);
    cudaGetSymbolAddress((void**)&qh,  g_qh);
    cudaGetSymbolAddress((void**)&kh,  g_kh);
    cudaGetSymbolAddress((void**)&vh,  g_vh);
    cudaGetSymbolAddress((void**)&xqh, g_xqh);
    cudaGetSymbolAddress((void**)&xkh, g_xkh);
    cudaGetSymbolAddress((void**)&xvh, g_xvh);
    cudaGetSymbolAddress((void**)&xoh, g_xoh);

    cudaFuncSetAttribute(gemm_h<1>,
                         cudaFuncAttributeMaxDynamicSharedMemorySize, GEMM_SMEM);
    cudaFuncSetAttribute(gemm_h<0>,
                         cudaFuncAttributeMaxDynamicSharedMemorySize, GEMM_SMEM);
    cudaFuncSetAttribute(flash_h,
                         cudaFuncAttributeMaxDynamicSharedMemorySize, FLASH_SMEM);

    // fp32 -> fp16 conversions
    const int WN4 = DIM * DIM / 4;      // 262144
    const int XN4 = MTOT * DIM / 4;     // 1048576
    dim3 cw_grid(WN4 / 256, 4);
    cvt_w4<<<cw_grid, 256>>>((const float4*)wq, (const float4*)wk,
                             (const float4*)wv, (const float4*)wo,
                             (__half2*)wh, WN4);
    dim3 ci_grid(XN4 / 256, 3);
    cvt_in3<<<ci_grid, 256>>>((const float4*)q, (const float4*)k, (const float4*)v,
                              (__half2*)qh, (__half2*)kh, (__half2*)vh);

    const __half* wqh = wh;
    const __half* wkh = wh + (size_t)DIM * DIM;
    const __half* wvh = wh + (size_t)2 * DIM * DIM;
    const __half* woh = wh + (size_t)3 * DIM * DIM;

    // QKV projections (fp16 out; q scaled by 1/8 for attention)
    dim3 qkv_grid(DIM / 128, MTOT / 128, 3);   // (8, 32, 3)
    gemm_h<1><<<qkv_grid, 128, GEMM_SMEM>>>(qh, kh, vh, wqh, wkh, wvh,
                                            xqh, xkh, xvh,
                                            0.125f, 1.0f, 1.0f, MTOT, DIM, DIM);

    dim3 flash_grid(SEQ / FQ, BATCH * NH);     // (16, 32)
    flash_h<<<flash_grid, 256, FLASH_SMEM>>>(xqh, xkh, xvh, xoh);

    // O projection (fp32 output)
    dim3 o_grid(DIM / 128, MTOT / 128, 1);     // (8, 32)
    gemm_h<0><<<o_grid, 128, GEMM_SMEM>>>(xoh, xoh, xoh, woh, woh, woh,
                                          out, out, out,
                                          1.0f, 1.0f, 1.0f, MTOT, DIM, DIM);
}

// round 17
// speedup vs baseline: 1.8593x; 1.0390x over previous
#include <cuda_runtime.h>
#include <cuda_fp16.h>
#include <math.h>

#define DIM 1024
#define NH 16
#define HD 64
#define BATCH 2
#define SEQ 2048
#define MTOT (BATCH * SEQ)   // 4096

// Scratch (device globals: allowed; no runtime allocation)
__device__ __half g_wh[4 * DIM * DIM];    // fp16 weights (wq,wk,wv,wo)
__device__ __half g_qh[MTOT * DIM];       // fp16 inputs
__device__ __half g_kh[MTOT * DIM];
__device__ __half g_vh[MTOT * DIM];
__device__ __half g_xqh[MTOT * DIM];      // fp16 projections
__device__ __half g_xkh[MTOT * DIM];
__device__ __half g_xvh[MTOT * DIM];
__device__ __half g_xoh[MTOT * DIM];      // fp16 attention output

__device__ __forceinline__ void mma_f16(float* c, const unsigned* a, const unsigned* b) {
    asm volatile(
        "mma.sync.aligned.m16n8k16.row.col.f32.f16.f16.f32 "
        "{%0,%1,%2,%3}, {%4,%5,%6,%7}, {%8,%9}, {%0,%1,%2,%3};\n"
        : "+f"(c[0]), "+f"(c[1]), "+f"(c[2]), "+f"(c[3])
        : "r"(a[0]), "r"(a[1]), "r"(a[2]), "r"(a[3]), "r"(b[0]), "r"(b[1]));
}

__device__ __forceinline__ void ldsm_x4(unsigned& r0, unsigned& r1,
                                        unsigned& r2, unsigned& r3, unsigned addr) {
    asm volatile("ldmatrix.sync.aligned.m8n8.x4.shared.b16 {%0,%1,%2,%3}, [%4];"
                 : "=r"(r0), "=r"(r1), "=r"(r2), "=r"(r3) : "r"(addr));
}
__device__ __forceinline__ void ldsm_x4_t(unsigned& r0, unsigned& r1,
                                          unsigned& r2, unsigned& r3, unsigned addr) {
    asm volatile("ldmatrix.sync.aligned.m8n8.x4.trans.shared.b16 {%0,%1,%2,%3}, [%4];"
                 : "=r"(r0), "=r"(r1), "=r"(r2), "=r"(r3) : "r"(addr));
}

__device__ __forceinline__ void cp_async16(void* smem_dst, const void* gptr) {
    unsigned s = (unsigned)__cvta_generic_to_shared(smem_dst);
    asm volatile("cp.async.cg.shared.global [%0], [%1], 16;\n" :: "r"(s), "l"(gptr));
}
__device__ __forceinline__ void cp_commit() {
    asm volatile("cp.async.commit_group;\n");
}
__device__ __forceinline__ void cp_wait0() { asm volatile("cp.async.wait_group 0;\n"); }
__device__ __forceinline__ void cp_wait1() { asm volatile("cp.async.wait_group 1;\n"); }

__device__ __forceinline__ float ex2(float x) {
    float r;
    asm("ex2.approx.f32 %0, %1;" : "=f"(r) : "f"(x));
    return r;
}
__device__ __forceinline__ unsigned packh2(float a, float b) {
    __half2 h = __floats2half2_rn(a, b);
    return *reinterpret_cast<unsigned*>(&h);
}

// ---------------------------------------------------------------------------
// fp32 -> fp16 conversion passes
// ---------------------------------------------------------------------------
__global__ void __launch_bounds__(256) cvt_w4(
    const float4* __restrict__ w0, const float4* __restrict__ w1,
    const float4* __restrict__ w2, const float4* __restrict__ w3,
    __half2* __restrict__ dst, int n4)
{
    const int y = blockIdx.y;
    const float4* src = (y == 0) ? w0 : (y == 1) ? w1 : (y == 2) ? w2 : w3;
    const int i = blockIdx.x * 256 + threadIdx.x;
    float4 v = src[i];
    __half2* d = dst + (size_t)y * n4 * 2;
    d[2 * i]     = __floats2half2_rn(v.x, v.y);
    d[2 * i + 1] = __floats2half2_rn(v.z, v.w);
}

__global__ void __launch_bounds__(256) cvt_in3(
    const float4* __restrict__ s0, const float4* __restrict__ s1,
    const float4* __restrict__ s2,
    __half2* __restrict__ d0, __half2* __restrict__ d1, __half2* __restrict__ d2)
{
    const int y = blockIdx.y;
    const float4* src = (y == 0) ? s0 : (y == 1) ? s1 : s2;
    __half2* d = (y == 0) ? d0 : (y == 1) ? d1 : d2;
    const int i = blockIdx.x * 256 + threadIdx.x;
    float4 v = src[i];
    d[2 * i]     = __floats2half2_rn(v.x, v.y);
    d[2 * i + 1] = __floats2half2_rn(v.z, v.w);
}

// ---------------------------------------------------------------------------
// FP16 NT GEMM (unchanged from R15): CTA 128x128, 128 threads (4 warps of
// 64x64), BK=32, 3-stage cp.async, frag double-buffering, 2 CTAs/SM.
// ---------------------------------------------------------------------------
#define LDH 40
#define STGH ((128 + 128) * LDH)
#define GEMM_SMEM (3 * STGH * 2)   // 61440 bytes

template <int OUT_HALF>
__global__ void __launch_bounds__(128, 2) gemm_h(
    const __half* __restrict__ A0, const __half* __restrict__ A1, const __half* __restrict__ A2,
    const __half* __restrict__ W0, const __half* __restrict__ W1, const __half* __restrict__ W2,
    void* __restrict__ C0, void* __restrict__ C1, void* __restrict__ C2,
    float s0, float s1, float s2, int M, int N, int K)
{
    extern __shared__ __half smh[];
    const int z = blockIdx.z;
    const __half* A = (z == 0) ? A0 : (z == 1) ? A1 : A2;
    const __half* W = (z == 0) ? W0 : (z == 1) ? W1 : W2;
    void* Cv = (z == 0) ? C0 : (z == 1) ? C1 : C2;
    const float sc = (z == 0) ? s0 : (z == 1) ? s1 : s2;

    const int tid = threadIdx.x;
    const int warp = tid >> 5, lane = tid & 31;
    const int g = lane >> 2, t = lane & 3;
    const int lm = lane >> 3, lr8 = lane & 7;
    const int wm = (warp & 1) * 64;
    const int wn = (warp >> 1) * 64;
    const int bm = blockIdx.y * 128, bn = blockIdx.x * 128;

    const unsigned smem_u = (unsigned)__cvta_generic_to_shared(smh);
    const unsigned aoff = ((wm + (lm & 1) * 8 + lr8) * LDH + (lm >> 1) * 8) * 2;
    const unsigned boff = ((wn + (lm >> 1) * 8 + lr8) * LDH + (lm & 1) * 8) * 2;

    float acc[4][8][4] = {};

    auto load_stage = [&](int s) {
        __half* As = smh + (s % 3) * STGH;
        __half* Bs = As + 128 * LDH;
        const int k0 = s * 32;
#pragma unroll
        for (int j = 0; j < 4; j++) {
            const int cid = tid + j * 128;
            const int row = cid >> 2, c16 = cid & 3;
            cp_async16(As + row * LDH + c16 * 8, A + (size_t)(bm + row) * K + k0 + c16 * 8);
            cp_async16(Bs + row * LDH + c16 * 8, W + (size_t)(bn + row) * K + k0 + c16 * 8);
        }
        cp_commit();
    };

    load_stage(0);
    load_stage(1);

    unsigned afr[2][4][4], bfr[2][8][2];

    const int niter = K / 32;
#pragma unroll 1
    for (int it = 0; it < niter; it++) {
        if (it + 1 < niter) cp_wait1(); else cp_wait0();
        __syncthreads();
        if (it + 2 < niter) load_stage(it + 2);

        const unsigned Ab = smem_u + (it % 3) * STGH * 2 + aoff;
        const unsigned Bb = smem_u + ((it % 3) * STGH + 128 * LDH) * 2 + boff;

#pragma unroll
        for (int mt = 0; mt < 4; mt++)
            ldsm_x4(afr[0][mt][0], afr[0][mt][1], afr[0][mt][2], afr[0][mt][3],
                    Ab + (mt * 16 * LDH) * 2);
#pragma unroll
        for (int p = 0; p < 4; p++)
            ldsm_x4(bfr[0][2 * p][0], bfr[0][2 * p][1],
                    bfr[0][2 * p + 1][0], bfr[0][2 * p + 1][1],
                    Bb + (p * 16 * LDH) * 2);

#pragma unroll
        for (int ks = 0; ks < 2; ks++) {
            const int cur = ks & 1, nxt = cur ^ 1;
            if (ks == 0) {
#pragma unroll
                for (int mt = 0; mt < 4; mt++)
                    ldsm_x4(afr[nxt][mt][0], afr[nxt][mt][1],
                            afr[nxt][mt][2], afr[nxt][mt][3],
                            Ab + (mt * 16 * LDH + 16) * 2);
#pragma unroll
                for (int p = 0; p < 4; p++)
                    ldsm_x4(bfr[nxt][2 * p][0], bfr[nxt][2 * p][1],
                            bfr[nxt][2 * p + 1][0], bfr[nxt][2 * p + 1][1],
                            Bb + (p * 16 * LDH + 16) * 2);
            }
#pragma unroll
            for (int mt = 0; mt < 4; mt++)
#pragma unroll
                for (int nt = 0; nt < 8; nt++)
                    mma_f16(acc[mt][nt], afr[cur][mt], bfr[cur][nt]);
        }
    }

#pragma unroll
    for (int mt = 0; mt < 4; mt++)
#pragma unroll
        for (int nt = 0; nt < 8; nt++) {
            const int row = bm + wm + mt * 16 + g;
            const int col = bn + wn + nt * 8 + 2 * t;
            const float v0 = acc[mt][nt][0] * sc, v1 = acc[mt][nt][1] * sc;
            const float v2 = acc[mt][nt][2] * sc, v3 = acc[mt][nt][3] * sc;
            if (OUT_HALF) {
                __half* C = (__half*)Cv;
                *(__half2*)&C[(size_t)row * N + col] = __floats2half2_rn(v0, v1);
                *(__half2*)&C[(size_t)(row + 8) * N + col] = __floats2half2_rn(v2, v3);
            } else {
                float* C = (float*)Cv;
                *(float2*)&C[(size_t)row * N + col] = make_float2(v0, v1);
                *(float2*)&C[(size_t)(row + 8) * N + col] = make_float2(v2, v3);
            }
        }
}

// ---------------------------------------------------------------------------
// FP16 flash attention, REGISTER-P: the S fragment a thread owns IS the PV
// A-fragment, so P never touches smem (pack exp'd floats to half2 directly).
// Softmax in exp2 domain (log2e folded into q pre-scale) -> raw ex2.approx.
// FQ=128 (8 warps x 16 rows), KV tiles 64, 3-stage cp.async K/V ring, 2 CTAs/SM.
// ---------------------------------------------------------------------------
#define FQ 128
#define FK 64
#define LDKH 72
#define LDVH 72
#define KBUFH (FK * LDKH)
#define VBUFH (FK * LDVH)
#define FLASH_SMEM (3 * (KBUFH + VBUFH) * 2)   // 55296 bytes

__global__ void __launch_bounds__(256, 2) flash_h(
    const __half* __restrict__ xq, const __half* __restrict__ xk,
    const __half* __restrict__ xv, __half* __restrict__ xo)
{
    extern __shared__ __half smh[];
    __half* Kst = smh;                    // 3 * KBUFH
    __half* Vst = Kst + 3 * KBUFH;        // 3 * VBUFH

    const int tid = threadIdx.x;
    const int warp = tid >> 5, lane = tid & 31;
    const int g = lane >> 2, t = lane & 3;
    const int lm = lane >> 3, lr8 = lane & 7;
    const int qt = gridDim.x - 1 - blockIdx.x;   // big tiles first
    const int bh = blockIdx.y;
    const int b = bh >> 4, h = bh & 15;
    const size_t base = (size_t)b * SEQ * DIM + (size_t)h * HD;
    const int qrow0 = qt * FQ + warp * 16;

    const unsigned smem_u = (unsigned)__cvta_generic_to_shared(smh);
    const unsigned koff = (((lm >> 1) * 8 + lr8) * LDKH + (lm & 1) * 8) * 2;
    const unsigned voff = (unsigned)(3 * KBUFH * 2) +
        (((lm & 1) * 8 + lr8) * LDVH + (lm >> 1) * 8) * 2;

    const __half* kbase = xk + base;
    const __half* vbase = xv + base;
    const int nkt = 2 * (qt + 1);

    auto load_kv = [&](int s) {
        __half* kd = Kst + (s % 3) * KBUFH;
        __half* vd = Vst + (s % 3) * VBUFH;
#pragma unroll
        for (int j = 0; j < 2; j++) {
            const int cid = tid + j * 256;
            const int row = cid >> 3, c16 = cid & 7;
            const size_t go = (size_t)(s * FK + row) * DIM + c16 * 8;
            cp_async16(kd + row * LDKH + c16 * 8, kbase + go);
            cp_async16(vd + row * LDVH + c16 * 8, vbase + go);
        }
        cp_commit();
    };

    load_kv(0);
    if (nkt > 1) load_kv(1);

    // Q fragments (xq pre-scaled by 0.125*log2e in the QKV GEMM epilogue)
    unsigned qf[4][4];
    {
        const __half* q0 = xq + base + (size_t)(qrow0 + g) * DIM;
        const __half* q1 = q0 + (size_t)8 * DIM;
#pragma unroll
        for (int c = 0; c < 4; c++) {
            qf[c][0] = *(const unsigned*)(q0 + c * 16 + 2 * t);
            qf[c][1] = *(const unsigned*)(q1 + c * 16 + 2 * t);
            qf[c][2] = *(const unsigned*)(q0 + c * 16 + 2 * t + 8);
            qf[c][3] = *(const unsigned*)(q1 + c * 16 + 2 * t + 8);
        }
    }

    float o[8][4] = {};
    float m0 = -1e30f, m1 = -1e30f, l0 = 0.f, l1 = 0.f;

#pragma unroll 1
    for (int kt = 0; kt < nkt; kt++) {
        if (kt + 1 < nkt) cp_wait1(); else cp_wait0();
        __syncthreads();   // tile kt ready; buffer (kt+2)%3's last reader done
        if (kt + 2 < nkt) load_kv(kt + 2);

        if (kt * FK > qrow0 + 15) continue;   // fully masked for this warp

        const unsigned Kb = smem_u + (kt % 3) * KBUFH * 2 + koff;

        // S = Q @ K^T  (fp32 accum; log2 domain)
        float s[8][4] = {};
#pragma unroll
        for (int c = 0; c < 4; c++) {
            unsigned bfr[8][2];
#pragma unroll
            for (int p = 0; p < 4; p++)
                ldsm_x4(bfr[2 * p][0], bfr[2 * p][1],
                        bfr[2 * p + 1][0], bfr[2 * p + 1][1],
                        Kb + (p * 16 * LDKH + c * 16) * 2);
#pragma unroll
            for (int nt = 0; nt < 8; nt++)
                mma_f16(s[nt], qf[c], bfr[nt]);
        }

        // Causal mask (tiles straddling the diagonal)
        if (kt * FK + FK - 1 > qrow0) {
            const int rg0 = qrow0 + g, rg1 = qrow0 + g + 8;
#pragma unroll
            for (int nt = 0; nt < 8; nt++) {
                const int col = kt * FK + nt * 8 + 2 * t;
                if (col > rg0)     s[nt][0] = -1e30f;
                if (col + 1 > rg0) s[nt][1] = -1e30f;
                if (col > rg1)     s[nt][2] = -1e30f;
                if (col + 1 > rg1) s[nt][3] = -1e30f;
            }
        }

        // Online softmax (exp2 domain)
        float mx0 = -1e30f, mx1 = -1e30f;
#pragma unroll
        for (int nt = 0; nt < 8; nt++) {
            mx0 = fmaxf(mx0, fmaxf(s[nt][0], s[nt][1]));
            mx1 = fmaxf(mx1, fmaxf(s[nt][2], s[nt][3]));
        }
        mx0 = fmaxf(mx0, __shfl_xor_sync(0xffffffffu, mx0, 1));
        mx0 = fmaxf(mx0, __shfl_xor_sync(0xffffffffu, mx0, 2));
        mx1 = fmaxf(mx1, __shfl_xor_sync(0xffffffffu, mx1, 1));
        mx1 = fmaxf(mx1, __shfl_xor_sync(0xffffffffu, mx1, 2));

        const float mn0 = fmaxf(m0, mx0);
        const float mn1 = fmaxf(m1, mx1);
        const float al0 = ex2(m0 - mn0);
        const float al1 = ex2(m1 - mn1);
        m0 = mn0; m1 = mn1;

        // exp in place: s becomes P (fp32)
        float sum0 = 0.f, sum1 = 0.f;
#pragma unroll
        for (int nt = 0; nt < 8; nt++) {
            s[nt][0] = ex2(s[nt][0] - mn0);
            s[nt][1] = ex2(s[nt][1] - mn0);
            s[nt][2] = ex2(s[nt][2] - mn1);
            s[nt][3] = ex2(s[nt][3] - mn1);
            sum0 += s[nt][0] + s[nt][1];
            sum1 += s[nt][2] + s[nt][3];
        }
        sum0 += __shfl_xor_sync(0xffffffffu, sum0, 1);
        sum0 += __shfl_xor_sync(0xffffffffu, sum0, 2);
        sum1 += __shfl_xor_sync(0xffffffffu, sum1, 1);
        sum1 += __shfl_xor_sync(0xffffffffu, sum1, 2);
        l0 = l0 * al0 + sum0;
        l1 = l1 * al1 + sum1;

#pragma unroll
        for (int nt = 0; nt < 8; nt++) {
            o[nt][0] *= al0; o[nt][1] *= al0;
            o[nt][2] *= al1; o[nt][3] *= al1;
        }

        // O += P @ V : A-fragments packed directly from the thread's own
        // S values (exact m16n8k16 A layout); V frags via ldmatrix.trans.
        const unsigned Vb = smem_u + voff + (kt % 3) * VBUFH * 2;
#pragma unroll
        for (int c = 0; c < 4; c++) {
            unsigned pafr[4];
            pafr[0] = packh2(s[2 * c][0], s[2 * c][1]);
            pafr[1] = packh2(s[2 * c][2], s[2 * c][3]);
            pafr[2] = packh2(s[2 * c + 1][0], s[2 * c + 1][1]);
            pafr[3] = packh2(s[2 * c + 1][2], s[2 * c + 1][3]);
            unsigned vfr[8][2];
#pragma unroll
            for (int p = 0; p < 4; p++)
                ldsm_x4_t(vfr[2 * p][0], vfr[2 * p][1],
                          vfr[2 * p + 1][0], vfr[2 * p + 1][1],
                          Vb + (c * 16 * LDVH + p * 16) * 2);
#pragma unroll
            for (int nt = 0; nt < 8; nt++)
                mma_f16(o[nt], pafr, vfr[nt]);
        }
    }

    // Normalize and write (fp16 for the O-projection GEMM)
    const float inv0 = 1.f / l0, inv1 = 1.f / l1;
    __half* d0 = xo + base + (size_t)(qrow0 + g) * DIM;
    __half* d1 = d0 + (size_t)8 * DIM;
#pragma unroll
    for (int nt = 0; nt < 8; nt++) {
        const int col = nt * 8 + 2 * t;
        *(__half2*)(d0 + col) = __floats2half2_rn(o[nt][0] * inv0, o[nt][1] * inv0);
        *(__half2*)(d1 + col) = __floats2half2_rn(o[nt][2] * inv1, o[nt][3] * inv1);
    }
}

// ---------------------------------------------------------------------------
// Launch
// ---------------------------------------------------------------------------
extern "C" void kernel_launch(void* const* d_in, const int* in_sizes, int n_in,
                              void* d_out, int out_size)
{
    const float* q  = (const float*)d_in[0];
    const float* k  = (const float*)d_in[1];
    const float* v  = (const float*)d_in[2];
    const float* wq = (const float*)d_in[3];
    const float* wk = (const float*)d_in[4];
    const float* wv = (const float*)d_in[5];
    const float* wo = (const float*)d_in[6];
    float* out = (float*)d_out;

    __half *wh, *qh, *kh, *vh, *xqh, *xkh, *xvh, *xoh;
    cudaGetSymbolAddress((void**)&wh,  g_wh);
    cudaGetSymbolAddress((void**)&qh,  g_qh);
    cudaGetSymbolAddress((void**)&kh,  g_kh);
    cudaGetSymbolAddress((void**)&vh,  g_vh);
    cudaGetSymbolAddress((void**)&xqh, g_xqh);
    cudaGetSymbolAddress((void**)&xkh, g_xkh);
    cudaGetSymbolAddress((void**)&xvh, g_xvh);
    cudaGetSymbolAddress((void**)&xoh, g_xoh);

    cudaFuncSetAttribute(gemm_h<1>,
                         cudaFuncAttributeMaxDynamicSharedMemorySize, GEMM_SMEM);
    cudaFuncSetAttribute(gemm_h<0>,
                         cudaFuncAttributeMaxDynamicSharedMemorySize, GEMM_SMEM);
    cudaFuncSetAttribute(flash_h,
                         cudaFuncAttributeMaxDynamicSharedMemorySize, FLASH_SMEM);

    // fp32 -> fp16 conversions
    const int WN4 = DIM * DIM / 4;
    const int XN4 = MTOT * DIM / 4;
    dim3 cw_grid(WN4 / 256, 4);
    cvt_w4<<<cw_grid, 256>>>((const float4*)wq, (const float4*)wk,
                             (const float4*)wv, (const float4*)wo,
                             (__half2*)wh, WN4);
    dim3 ci_grid(XN4 / 256, 3);
    cvt_in3<<<ci_grid, 256>>>((const float4*)q, (const float4*)k, (const float4*)v,
                              (__half2*)qh, (__half2*)kh, (__half2*)vh);

    const __half* wqh = wh;
    const __half* wkh = wh + (size_t)DIM * DIM;
    const __half* wvh = wh + (size_t)2 * DIM * DIM;
    const __half* woh = wh + (size_t)3 * DIM * DIM;

    // QKV projections (fp16 out; q pre-scaled by 0.125*log2e for exp2 softmax)
    const float QSCALE = 0.125f * 1.44269504088896f;
    dim3 qkv_grid(DIM / 128, MTOT / 128, 3);   // (8, 32, 3)
    gemm_h<1><<<qkv_grid, 128, GEMM_SMEM>>>(qh, kh, vh, wqh, wkh, wvh,
                                            xqh, xkh, xvh,
                                            QSCALE, 1.0f, 1.0f, MTOT, DIM, DIM);

    dim3 flash_grid(SEQ / FQ, BATCH * NH);     // (16, 32)
    flash_h<<<flash_grid, 256, FLASH_SMEM>>>(xqh, xkh, xvh, xoh);

    // O projection (fp32 output)
    dim3 o_grid(DIM / 128, MTOT / 128, 1);     // (8, 32)
    gemm_h<0><<<o_grid, 128, GEMM_SMEM>>>(xoh, xoh, xoh, woh, woh, woh,
                                          out, out, out,
                                          1.0f, 1.0f, 1.0f, MTOT, DIM, DIM);
}